// round 12
// baseline (speedup 1.0000x reference)
#include <cuda_runtime.h>
#include <cstdint>

// GRU_12962211299468 : B=65536, T=9, I=57, H=2, O=1, fp32
// Round 12: fused kernel, warp-private self-paced sub-tiles.
//   CTA = 288 threads (9 warps) owns 32 whole batch elements (65664 B of x).
//   Warp w: cp.async its own 32 rows (7296 B) -> wait own group -> __syncwarp
//           -> project 32 rows (6x57 dots) -> gates to smem sgx.
//   ONE __syncthreads, then warp 0 runs the 32-batch recurrence + FC.
// Combines R11's fusion (no 28 MB scratch, no 2nd launch) with K1's proven
// warp self-pacing (continuous DRAM stream at ~27 warps/SM).

#define T_STEPS 9
#define I_DIM   57
#define B_TOT   65536
#define NB      32                          // batches per CTA
#define NWARP   9
#define NTHR    (NWARP * 32)                // 288
#define RPW_FLT (32 * I_DIM)                // 1824 floats per warp sub-tile
#define RPW_V4  (RPW_FLT / 4)               // 456 chunks per warp
#define XFLT    (NB * T_STEPS * I_DIM)      // 16416 floats
#define WROW    60                          // padded W_ih row
#define SGXROW  57                          // sgx row stride (odd)
#define GRID    (B_TOT / NB)                // 2048

#define SW_OFF  XFLT
#define SGX_OFF (XFLT + 6 * WROW)
#define SMEM_FLOATS (SGX_OFF + NB * SGXROW)
#define SMEM_BYTES  (SMEM_FLOATS * 4)       // 74400 B

__device__ __forceinline__ uint32_t s2u(const void* p) {
    uint32_t a;
    asm("{ .reg .u64 t; cvta.to.shared.u64 t, %1; cvt.u32.u64 %0, t; }"
        : "=r"(a) : "l"(p));
    return a;
}
__device__ __forceinline__ void cp16(uint32_t dst, const float4* src) {
    asm volatile("cp.async.cg.shared.global [%0], [%1], 16;"
                 :: "r"(dst), "l"(src) : "memory");
}
__device__ __forceinline__ void cp_commit_wait0() {
    asm volatile("cp.async.commit_group;" ::: "memory");
    asm volatile("cp.async.wait_group 0;" ::: "memory");
}

__device__ __forceinline__ float sigf(float v) {
    return 1.0f / (1.0f + __expf(-v));
}
__device__ __forceinline__ float tanh_ex(float v) {
    return 1.0f - 2.0f / (__expf(2.0f * v) + 1.0f);
}

__global__ __launch_bounds__(NTHR, 3) void gru_fused(
    const float* __restrict__ x,
    const float* __restrict__ Wih,   // [6,57]
    const float* __restrict__ Whh,   // [6,2]
    const float* __restrict__ bih,   // [6]
    const float* __restrict__ bhh,   // [6]
    const float* __restrict__ fcw,   // [2]
    const float* __restrict__ fcb,   // [1]
    float* __restrict__ out)         // [B]
{
    extern __shared__ __align__(16) float sm[];
    float* sx  = sm;                 // x tile
    float* sw  = sm + SW_OFF;        // W_ih padded
    float* sgx = sm + SGX_OFF;       // gate pre-activations [32][57]

    const int tid  = threadIdx.x;
    const int wid  = tid >> 5;
    const int lane = tid & 31;
    const int b0   = blockIdx.x * NB;

    // ---- per-warp staging of this warp's 32 rows (1824 contiguous floats) ----
    {
        const float4* src = reinterpret_cast<const float4*>(x) +
                            (size_t)blockIdx.x * (XFLT / 4) + wid * RPW_V4;
        const uint32_t sb = s2u(sx + wid * RPW_FLT);
#pragma unroll
        for (int k = 0; k < 15; ++k) {
            int j = lane + 32 * k;
            if (j < RPW_V4) cp16(sb + 16u * (uint32_t)j, src + j);
        }
    }

    // ---- stage W_ih into smem while cp.async is in flight ----
    // (each warp fills a disjoint slice; visibility for this warp's own use is
    //  immediate, and the projection below only reads its own warp's needs
    //  after __syncwarp... but weights are shared across warps -> must be
    //  written before any warp reads them. Use warp 0..? Simplest safe scheme:
    //  every warp writes the FULL sw array redundantly -- same values, no race.)
    for (int j = lane; j < 6 * WROW; j += 32) {
        int g = j / WROW;
        int i = j - g * WROW;
        sw[j] = (i < I_DIM) ? Wih[g * I_DIM + i] : 0.0f;
    }

    const float bi0 = bih[0], bi1 = bih[1], bi2 = bih[2];
    const float bi3 = bih[3], bi4 = bih[4], bi5 = bih[5];

    cp_commit_wait0();     // wait for THIS thread's (warp's) copies only
    __syncwarp();

    // ---- projection: lane's row r = 32*wid + lane ----
    {
        const int r = 32 * wid + lane;
        const float* row = &sx[r * I_DIM];      // stride 57: conflict-free

        float g0 = bi0, g1 = bi1, g2 = bi2, g3 = bi3, g4 = bi4, g5 = bi5;
#pragma unroll
        for (int c = 0; c < 14; ++c) {
            float x0 = row[4 * c + 0];
            float x1 = row[4 * c + 1];
            float x2 = row[4 * c + 2];
            float x3 = row[4 * c + 3];
            float4 v;
            v = *reinterpret_cast<const float4*>(&sw[0 * WROW + 4 * c]);
            g0 += v.x * x0 + v.y * x1 + v.z * x2 + v.w * x3;
            v = *reinterpret_cast<const float4*>(&sw[1 * WROW + 4 * c]);
            g1 += v.x * x0 + v.y * x1 + v.z * x2 + v.w * x3;
            v = *reinterpret_cast<const float4*>(&sw[2 * WROW + 4 * c]);
            g2 += v.x * x0 + v.y * x1 + v.z * x2 + v.w * x3;
            v = *reinterpret_cast<const float4*>(&sw[3 * WROW + 4 * c]);
            g3 += v.x * x0 + v.y * x1 + v.z * x2 + v.w * x3;
            v = *reinterpret_cast<const float4*>(&sw[4 * WROW + 4 * c]);
            g4 += v.x * x0 + v.y * x1 + v.z * x2 + v.w * x3;
            v = *reinterpret_cast<const float4*>(&sw[5 * WROW + 4 * c]);
            g5 += v.x * x0 + v.y * x1 + v.z * x2 + v.w * x3;
        }
        {
            float xs = row[56];
            g0 += sw[0 * WROW + 56] * xs;
            g1 += sw[1 * WROW + 56] * xs;
            g2 += sw[2 * WROW + 56] * xs;
            g3 += sw[3 * WROW + 56] * xs;
            g4 += sw[4 * WROW + 56] * xs;
            g5 += sw[5 * WROW + 56] * xs;
        }

        const int b = r / 9;           // batch within CTA
        const int t = r - 9 * b;
        float* gq = &sgx[b * SGXROW + 6 * t];
        gq[0] = g0; gq[1] = g1; gq[2] = g2;
        gq[3] = g3; gq[4] = g4; gq[5] = g5;
    }

    __syncthreads();   // the only block barrier: sgx complete

    // ---- recurrence + FC: warp 0, lane = batch ----
    if (wid == 0) {
        const float w00 = Whh[0],  w01 = Whh[1];
        const float w10 = Whh[2],  w11 = Whh[3];
        const float w20 = Whh[4],  w21 = Whh[5];
        const float w30 = Whh[6],  w31 = Whh[7];
        const float w40 = Whh[8],  w41 = Whh[9];
        const float w50 = Whh[10], w51 = Whh[11];
        const float bh0 = bhh[0], bh1 = bhh[1], bh2 = bhh[2];
        const float bh3 = bhh[3], bh4 = bhh[4], bh5 = bhh[5];

        const float* gp = &sgx[lane * SGXROW];   // stride 57: conflict-free
        float h0 = 0.0f, h1 = 0.0f;

#pragma unroll
        for (int t = 0; t < T_STEPS; ++t) {
            float q0 = gp[6 * t + 0];
            float q1 = gp[6 * t + 1];
            float q2 = gp[6 * t + 2];
            float q3 = gp[6 * t + 3];
            float q4 = gp[6 * t + 4];
            float q5 = gp[6 * t + 5];

            float a0 = w00 * h0 + w01 * h1 + bh0;
            float a1 = w10 * h0 + w11 * h1 + bh1;
            float a2 = w20 * h0 + w21 * h1 + bh2;
            float a3 = w30 * h0 + w31 * h1 + bh3;
            float a4 = w40 * h0 + w41 * h1 + bh4;
            float a5 = w50 * h0 + w51 * h1 + bh5;

            float r0 = sigf(q0 + a0);
            float r1 = sigf(q1 + a1);
            float z0 = sigf(q2 + a2);
            float z1 = sigf(q3 + a3);
            float n0 = tanh_ex(q4 + r0 * a4);
            float n1 = tanh_ex(q5 + r1 * a5);

            h0 = (1.0f - z0) * n0 + z0 * h0;
            h1 = (1.0f - z1) * n1 + z1 * h1;
        }

        out[b0 + lane] = fcw[0] * h0 + fcw[1] * h1 + fcb[0];   // coalesced
    }
}

extern "C" void kernel_launch(void* const* d_in, const int* in_sizes, int n_in,
                              void* d_out, int out_size) {
    const float* x   = (const float*)d_in[0];
    const float* Wih = (const float*)d_in[1];
    const float* Whh = (const float*)d_in[2];
    const float* bih = (const float*)d_in[3];
    const float* bhh = (const float*)d_in[4];
    const float* fcw = (const float*)d_in[5];
    const float* fcb = (const float*)d_in[6];
    float* out = (float*)d_out;

    (void)in_sizes; (void)n_in; (void)out_size;

    static int configured = 0;
    if (!configured) {
        cudaFuncSetAttribute(gru_fused,
                             cudaFuncAttributeMaxDynamicSharedMemorySize,
                             SMEM_BYTES);
        configured = 1;
    }

    gru_fused<<<GRID, NTHR, SMEM_BYTES>>>(x, Wih, Whh, bih, bhh, fcw, fcb, out);
}

// round 13
// speedup vs baseline: 1.2874x; 1.2874x over previous
#include <cuda_runtime.h>
#include <cstdint>

// GRU_12962211299468 : B=65536, T=9, I=57, H=2, O=1, fp32
// Round 13: keep the proven split (R10 K1 @ ~29us), fix K2's latency bound.
// gx scratch re-laid out as [14 chunks][B][4 floats] (chunk = (6t+g)/4):
//   K2: 14 coalesced, independent LDG.128 per thread (512B contiguous per
//       warp-instr) -> 14-deep MLP, ~99 KB/SM in flight -> pure stream.
//   K1: row (b,t) stores its 6 gates as one STG.128 + one STG.64 (the span
//       6t..6t+5 covers exactly 2 chunks; alignment holds for both parities).

#define T_STEPS 9
#define I_DIM   57
#define B_TOT   65536
#define NROWS_T (B_TOT * T_STEPS)       // 589824 rows
#define RPW     32                      // rows per warp
#define RPW_FLT (RPW * I_DIM)           // 1824 floats per warp tile
#define RPW_V4  (RPW_FLT / 4)           // 456 chunks
#define WARPS_K1 (NROWS_T / RPW)        // 18432
#define CWARPS  4
#define K1_THR  (CWARPS * 32)           // 128
#define K1_GRID (WARPS_K1 / CWARPS)     // 4608
#define WROW    60
#define NCHUNK  14                      // ceil(54/4) gate chunks
#define B4      (B_TOT * 4)             // floats per chunk plane

__device__ __align__(16) float g_gx[(size_t)NCHUNK * B4];   // 14.7 MB scratch

__device__ __forceinline__ uint32_t s2u(const void* p) {
    uint32_t a;
    asm("{ .reg .u64 t; cvta.to.shared.u64 t, %1; cvt.u32.u64 %0, t; }"
        : "=r"(a) : "l"(p));
    return a;
}
__device__ __forceinline__ void cp16(uint32_t dst, const float4* src) {
    asm volatile("cp.async.cg.shared.global [%0], [%1], 16;"
                 :: "r"(dst), "l"(src) : "memory");
}
__device__ __forceinline__ void cp_commit_wait0() {
    asm volatile("cp.async.commit_group;" ::: "memory");
    asm volatile("cp.async.wait_group 0;" ::: "memory");
}

__device__ __forceinline__ float sigf(float v) {
    return 1.0f / (1.0f + __expf(-v));
}
__device__ __forceinline__ float tanh_ex(float v) {
    return 1.0f - 2.0f / (__expf(2.0f * v) + 1.0f);
}

// ---------------------------------------------------------------- K1 ----
__global__ __launch_bounds__(K1_THR, 7) void gru_proj(
    const float* __restrict__ x,
    const float* __restrict__ Wih,   // [6,57]
    const float* __restrict__ bih)   // [6]
{
    __shared__ __align__(16) float sx[CWARPS][RPW_FLT];  // 4 x 7296 B
    __shared__ float sw[6 * WROW];                       // 1440 B

    const int tid  = threadIdx.x;
    const int wid  = tid >> 5;
    const int lane = tid & 31;

    for (int j = tid; j < 6 * WROW; j += K1_THR) {
        int g = j / WROW;
        int i = j - g * WROW;
        sw[j] = (i < I_DIM) ? Wih[g * I_DIM + i] : 0.0f;
    }
    __syncthreads();

    const float bi0 = bih[0], bi1 = bih[1], bi2 = bih[2];
    const float bi3 = bih[3], bi4 = bih[4], bi5 = bih[5];

    const int wg = blockIdx.x * CWARPS + wid;      // global warp id

    // ---- stage warp tile via cp.async: zero reg pressure, full MLP ----
    {
        const float4* src = reinterpret_cast<const float4*>(x) + (size_t)wg * RPW_V4;
        const uint32_t sb = s2u(&sx[wid][0]);
#pragma unroll
        for (int k = 0; k < 15; ++k) {
            int j = lane + 32 * k;
            if (j < RPW_V4) cp16(sb + 16u * (uint32_t)j, src + j);
        }
    }
    cp_commit_wait0();
    __syncwarp();

    // ---- lane = one row: 6 x 57 dot products ----
    const float* row = &sx[wid][lane * I_DIM];     // stride 57: conflict-free

    float g0 = bi0, g1 = bi1, g2 = bi2, g3 = bi3, g4 = bi4, g5 = bi5;
#pragma unroll
    for (int c = 0; c < 14; ++c) {
        float x0 = row[4 * c + 0];
        float x1 = row[4 * c + 1];
        float x2 = row[4 * c + 2];
        float x3 = row[4 * c + 3];
        float4 v;
        v = *reinterpret_cast<const float4*>(&sw[0 * WROW + 4 * c]);
        g0 += v.x * x0 + v.y * x1 + v.z * x2 + v.w * x3;
        v = *reinterpret_cast<const float4*>(&sw[1 * WROW + 4 * c]);
        g1 += v.x * x0 + v.y * x1 + v.z * x2 + v.w * x3;
        v = *reinterpret_cast<const float4*>(&sw[2 * WROW + 4 * c]);
        g2 += v.x * x0 + v.y * x1 + v.z * x2 + v.w * x3;
        v = *reinterpret_cast<const float4*>(&sw[3 * WROW + 4 * c]);
        g3 += v.x * x0 + v.y * x1 + v.z * x2 + v.w * x3;
        v = *reinterpret_cast<const float4*>(&sw[4 * WROW + 4 * c]);
        g4 += v.x * x0 + v.y * x1 + v.z * x2 + v.w * x3;
        v = *reinterpret_cast<const float4*>(&sw[5 * WROW + 4 * c]);
        g5 += v.x * x0 + v.y * x1 + v.z * x2 + v.w * x3;
    }
    {
        float xs = row[56];
        g0 += sw[0 * WROW + 56] * xs;
        g1 += sw[1 * WROW + 56] * xs;
        g2 += sw[2 * WROW + 56] * xs;
        g3 += sw[3 * WROW + 56] * xs;
        g4 += sw[4 * WROW + 56] * xs;
        g5 += sw[5 * WROW + 56] * xs;
    }

    // ---- scatter to chunk-interleaved gx ----
    // s = 6t+g ; chunk c = s/4, slot j = s%4 ; plane stride B4, batch slot b*4
    const int r = wg * RPW + lane;                 // global row = 9b + t
    const int b = r / 9;
    const int t = r - 9 * b;
    const int c0 = (6 * t) >> 2;                   // first chunk of this row
    float* base = &g_gx[(size_t)c0 * B4 + b * 4];
    if ((t & 1) == 0) {
        // 6t % 4 == 0 : [g0 g1 g2 g3] in c0, [g4 g5] at c0+1 slots 0..1
        *reinterpret_cast<float4*>(base) = make_float4(g0, g1, g2, g3);
        *reinterpret_cast<float2*>(base + B4) = make_float2(g4, g5);
    } else {
        // 6t % 4 == 2 : [g0 g1] in c0 slots 2..3, [g2 g3 g4 g5] in c0+1
        *reinterpret_cast<float2*>(base + 2) = make_float2(g0, g1);
        *reinterpret_cast<float4*>(base + B4) = make_float4(g2, g3, g4, g5);
    }
}

// ---------------------------------------------------------------- K2 ----
__global__ __launch_bounds__(128, 1) void gru_recur(
    const float* __restrict__ Whh,   // [6,2]
    const float* __restrict__ bhh,   // [6]
    const float* __restrict__ fcw,   // [2]
    const float* __restrict__ fcb,   // [1]
    float* __restrict__ out)         // [B]
{
    const int b = blockIdx.x * 128 + threadIdx.x;

    // 14 coalesced, independent LDG.128 (consecutive b -> contiguous 512B/warp)
    float v[NCHUNK * 4];
#pragma unroll
    for (int c = 0; c < NCHUNK; ++c)
        reinterpret_cast<float4*>(v)[c] =
            __ldg(reinterpret_cast<const float4*>(&g_gx[(size_t)c * B4 + b * 4]));

    const float w00 = __ldg(Whh + 0),  w01 = __ldg(Whh + 1);
    const float w10 = __ldg(Whh + 2),  w11 = __ldg(Whh + 3);
    const float w20 = __ldg(Whh + 4),  w21 = __ldg(Whh + 5);
    const float w30 = __ldg(Whh + 6),  w31 = __ldg(Whh + 7);
    const float w40 = __ldg(Whh + 8),  w41 = __ldg(Whh + 9);
    const float w50 = __ldg(Whh + 10), w51 = __ldg(Whh + 11);
    const float bh0 = __ldg(bhh + 0), bh1 = __ldg(bhh + 1), bh2 = __ldg(bhh + 2);
    const float bh3 = __ldg(bhh + 3), bh4 = __ldg(bhh + 4), bh5 = __ldg(bhh + 5);

    float h0 = 0.0f, h1 = 0.0f;
#pragma unroll
    for (int t = 0; t < T_STEPS; ++t) {
        float q0 = v[6 * t + 0];
        float q1 = v[6 * t + 1];
        float q2 = v[6 * t + 2];
        float q3 = v[6 * t + 3];
        float q4 = v[6 * t + 4];
        float q5 = v[6 * t + 5];

        float a0 = w00 * h0 + w01 * h1 + bh0;
        float a1 = w10 * h0 + w11 * h1 + bh1;
        float a2 = w20 * h0 + w21 * h1 + bh2;
        float a3 = w30 * h0 + w31 * h1 + bh3;
        float a4 = w40 * h0 + w41 * h1 + bh4;
        float a5 = w50 * h0 + w51 * h1 + bh5;

        float r0 = sigf(q0 + a0);
        float r1 = sigf(q1 + a1);
        float z0 = sigf(q2 + a2);
        float z1 = sigf(q3 + a3);
        float n0 = tanh_ex(q4 + r0 * a4);
        float n1 = tanh_ex(q5 + r1 * a5);

        h0 = (1.0f - z0) * n0 + z0 * h0;
        h1 = (1.0f - z1) * n1 + z1 * h1;
    }

    out[b] = __ldg(fcw + 0) * h0 + __ldg(fcw + 1) * h1 + __ldg(fcb);
}

extern "C" void kernel_launch(void* const* d_in, const int* in_sizes, int n_in,
                              void* d_out, int out_size) {
    const float* x   = (const float*)d_in[0];
    const float* Wih = (const float*)d_in[1];
    const float* Whh = (const float*)d_in[2];
    const float* bih = (const float*)d_in[3];
    const float* bhh = (const float*)d_in[4];
    const float* fcw = (const float*)d_in[5];
    const float* fcb = (const float*)d_in[6];
    float* out = (float*)d_out;

    (void)in_sizes; (void)n_in; (void)out_size;

    gru_proj<<<K1_GRID, K1_THR>>>(x, Wih, bih);
    gru_recur<<<B_TOT / 128, 128>>>(Whh, bhh, fcw, fcb, out);
}

// round 14
// speedup vs baseline: 1.3024x; 1.0117x over previous
#include <cuda_runtime.h>
#include <cstdint>

// GRU_12962211299468 : B=65536, T=9, I=57, H=2, O=1, fp32
// Round 14:
//  K1: gate math in packed fma.rn.f32x2 (FFMA2) -- 3 pair-accumulators,
//      weights pre-packed pairwise in smem; halves FFMA-pipe pressure.
//  K2: cp.async stages each thread's 14 gate chunks into smem (zero register
//      footprint -> guaranteed 14-deep MLP); thread reads back only its own
//      chunks, so no block barrier at all. Fixes the round-10/13 latency bind.

#define T_STEPS 9
#define I_DIM   57
#define B_TOT   65536
#define NROWS_T (B_TOT * T_STEPS)       // 589824 rows
#define RPW     32                      // rows per warp
#define RPW_FLT (RPW * I_DIM)           // 1824 floats per warp tile
#define RPW_V4  (RPW_FLT / 4)           // 456 chunks
#define WARPS_K1 (NROWS_T / RPW)        // 18432
#define CWARPS  4
#define K1_THR  (CWARPS * 32)           // 128
#define K1_GRID (WARPS_K1 / CWARPS)     // 4608
#define NCHUNK  14                      // ceil(54/4) gate chunks
#define B4      (B_TOT * 4)             // floats per chunk plane
#define PROW    120                     // packed-weight row: 60 pairs (floats)

__device__ __align__(16) float g_gx[(size_t)NCHUNK * B4];   // 14.7 MB scratch

typedef unsigned long long u64;

__device__ __forceinline__ uint32_t s2u(const void* p) {
    uint32_t a;
    asm("{ .reg .u64 t; cvta.to.shared.u64 t, %1; cvt.u32.u64 %0, t; }"
        : "=r"(a) : "l"(p));
    return a;
}
__device__ __forceinline__ void cp16(uint32_t dst, const void* src) {
    asm volatile("cp.async.cg.shared.global [%0], [%1], 16;"
                 :: "r"(dst), "l"(src) : "memory");
}
__device__ __forceinline__ void cp_commit_wait0() {
    asm volatile("cp.async.commit_group;" ::: "memory");
    asm volatile("cp.async.wait_group 0;" ::: "memory");
}
__device__ __forceinline__ u64 pack2(float lo, float hi) {
    u64 r;
    asm("mov.b64 %0, {%1, %2};" : "=l"(r) : "f"(lo), "f"(hi));
    return r;
}
__device__ __forceinline__ void unpack2(float& lo, float& hi, u64 v) {
    asm("mov.b64 {%0, %1}, %2;" : "=f"(lo), "=f"(hi) : "l"(v));
}
__device__ __forceinline__ void fma2(u64& d, u64 a, u64 b) {
    asm("fma.rn.f32x2 %0, %1, %2, %0;" : "+l"(d) : "l"(a), "l"(b));
}

__device__ __forceinline__ float sigf(float v) {
    return 1.0f / (1.0f + __expf(-v));
}
__device__ __forceinline__ float tanh_ex(float v) {
    return 1.0f - 2.0f / (__expf(2.0f * v) + 1.0f);
}

// ---------------------------------------------------------------- K1 ----
__global__ __launch_bounds__(K1_THR, 7) void gru_proj(
    const float* __restrict__ x,
    const float* __restrict__ Wih,   // [6,57]
    const float* __restrict__ bih)   // [6]
{
    __shared__ __align__(16) float sx[CWARPS][RPW_FLT];  // 4 x 7296 B
    __shared__ __align__(16) float swp[3 * PROW];        // pairwise-packed W_ih

    const int tid  = threadIdx.x;
    const int wid  = tid >> 5;
    const int lane = tid & 31;

    // pack weights: swp[p][2i], swp[p][2i+1] = W[2p][i], W[2p+1][i]
    for (int j = tid; j < 3 * (PROW / 2); j += K1_THR) {
        int p = j / (PROW / 2);
        int i = j - p * (PROW / 2);
        float a = 0.0f, b = 0.0f;
        if (i < I_DIM) {
            a = Wih[(2 * p) * I_DIM + i];
            b = Wih[(2 * p + 1) * I_DIM + i];
        }
        swp[p * PROW + 2 * i]     = a;
        swp[p * PROW + 2 * i + 1] = b;
    }
    __syncthreads();

    const u64 bi01 = pack2(bih[0], bih[1]);
    const u64 bi23 = pack2(bih[2], bih[3]);
    const u64 bi45 = pack2(bih[4], bih[5]);

    const int wg = blockIdx.x * CWARPS + wid;      // global warp id

    // ---- stage warp tile via cp.async ----
    {
        const float4* src = reinterpret_cast<const float4*>(x) + (size_t)wg * RPW_V4;
        const uint32_t sb = s2u(&sx[wid][0]);
#pragma unroll
        for (int k = 0; k < 15; ++k) {
            int j = lane + 32 * k;
            if (j < RPW_V4) cp16(sb + 16u * (uint32_t)j, src + j);
        }
    }
    cp_commit_wait0();
    __syncwarp();

    // ---- lane = one row: 3 packed gate-pair dot products ----
    const float* row = &sx[wid][lane * I_DIM];     // stride 57: conflict-free

    u64 a01 = bi01, a23 = bi23, a45 = bi45;
#pragma unroll
    for (int c = 0; c < 14; ++c) {
        float x0 = row[4 * c + 0];
        float x1 = row[4 * c + 1];
        float x2 = row[4 * c + 2];
        float x3 = row[4 * c + 3];
        u64 xx0 = pack2(x0, x0);
        u64 xx1 = pack2(x1, x1);
        u64 xx2 = pack2(x2, x2);
        u64 xx3 = pack2(x3, x3);

        {
            const float4* wp = reinterpret_cast<const float4*>(&swp[0 * PROW + 8 * c]);
            float4 wa = wp[0], wb = wp[1];
            fma2(a01, pack2(wa.x, wa.y), xx0);
            fma2(a01, pack2(wa.z, wa.w), xx1);
            fma2(a01, pack2(wb.x, wb.y), xx2);
            fma2(a01, pack2(wb.z, wb.w), xx3);
        }
        {
            const float4* wp = reinterpret_cast<const float4*>(&swp[1 * PROW + 8 * c]);
            float4 wa = wp[0], wb = wp[1];
            fma2(a23, pack2(wa.x, wa.y), xx0);
            fma2(a23, pack2(wa.z, wa.w), xx1);
            fma2(a23, pack2(wb.x, wb.y), xx2);
            fma2(a23, pack2(wb.z, wb.w), xx3);
        }
        {
            const float4* wp = reinterpret_cast<const float4*>(&swp[2 * PROW + 8 * c]);
            float4 wa = wp[0], wb = wp[1];
            fma2(a45, pack2(wa.x, wa.y), xx0);
            fma2(a45, pack2(wa.z, wa.w), xx1);
            fma2(a45, pack2(wb.x, wb.y), xx2);
            fma2(a45, pack2(wb.z, wb.w), xx3);
        }
    }
    {   // tail i = 56
        float xs = row[56];
        u64 xx = pack2(xs, xs);
        fma2(a01, *reinterpret_cast<const u64*>(&swp[0 * PROW + 112]), xx);
        fma2(a23, *reinterpret_cast<const u64*>(&swp[1 * PROW + 112]), xx);
        fma2(a45, *reinterpret_cast<const u64*>(&swp[2 * PROW + 112]), xx);
    }

    float g0, g1, g2, g3, g4, g5;
    unpack2(g0, g1, a01);
    unpack2(g2, g3, a23);
    unpack2(g4, g5, a45);

    // ---- scatter to chunk-interleaved gx ----
    const int r = wg * RPW + lane;                 // global row = 9b + t
    const int b = r / 9;
    const int t = r - 9 * b;
    const int c0 = (6 * t) >> 2;
    float* base = &g_gx[(size_t)c0 * B4 + b * 4];
    if ((t & 1) == 0) {
        *reinterpret_cast<float4*>(base) = make_float4(g0, g1, g2, g3);
        *reinterpret_cast<float2*>(base + B4) = make_float2(g4, g5);
    } else {
        *reinterpret_cast<float2*>(base + 2) = make_float2(g0, g1);
        *reinterpret_cast<float4*>(base + B4) = make_float4(g2, g3, g4, g5);
    }
}

// ---------------------------------------------------------------- K2 ----
__global__ __launch_bounds__(128, 8) void gru_recur(
    const float* __restrict__ Whh,   // [6,2]
    const float* __restrict__ bhh,   // [6]
    const float* __restrict__ fcw,   // [2]
    const float* __restrict__ fcb,   // [1]
    float* __restrict__ out)         // [B]
{
    __shared__ __align__(16) float sg[NCHUNK][128 * 4];   // 28672 B

    const int tid = threadIdx.x;
    const int b   = blockIdx.x * 128 + tid;

    // cp.async this thread's 14 gate chunks (coalesced across the warp,
    // zero register footprint -> all 14 in flight). Thread reads back ONLY
    // its own chunks, so wait_group 0 suffices -- no block barrier.
    {
        const uint32_t sb = s2u(sg);
#pragma unroll
        for (int c = 0; c < NCHUNK; ++c)
            cp16(sb + (uint32_t)(c * 2048 + tid * 16),
                 &g_gx[(size_t)c * B4 + (size_t)b * 4]);
    }

    const float w00 = __ldg(Whh + 0),  w01 = __ldg(Whh + 1);
    const float w10 = __ldg(Whh + 2),  w11 = __ldg(Whh + 3);
    const float w20 = __ldg(Whh + 4),  w21 = __ldg(Whh + 5);
    const float w30 = __ldg(Whh + 6),  w31 = __ldg(Whh + 7);
    const float w40 = __ldg(Whh + 8),  w41 = __ldg(Whh + 9);
    const float w50 = __ldg(Whh + 10), w51 = __ldg(Whh + 11);
    const float bh0 = __ldg(bhh + 0), bh1 = __ldg(bhh + 1), bh2 = __ldg(bhh + 2);
    const float bh3 = __ldg(bhh + 3), bh4 = __ldg(bhh + 4), bh5 = __ldg(bhh + 5);
    const float fw0 = __ldg(fcw + 0), fw1 = __ldg(fcw + 1), fb = __ldg(fcb);

    cp_commit_wait0();

    float h0 = 0.0f, h1 = 0.0f;
#pragma unroll
    for (int t = 0; t < T_STEPS; ++t) {
        const int s = 6 * t;
        // gates s..s+5 live in chunks s/4 and s/4+1 of this thread's column
        const float* col0 = &sg[(s >> 2) + 0][tid * 4];
        const float* col1 = &sg[(s >> 2) + 1][tid * 4];
        float q0, q1, q2, q3, q4, q5;
        if ((t & 1) == 0) {
            q0 = col0[0]; q1 = col0[1]; q2 = col0[2]; q3 = col0[3];
            q4 = col1[0]; q5 = col1[1];
        } else {
            q0 = col0[2]; q1 = col0[3];
            q2 = col1[0]; q3 = col1[1]; q4 = col1[2]; q5 = col1[3];
        }

        float a0 = w00 * h0 + w01 * h1 + bh0;
        float a1 = w10 * h0 + w11 * h1 + bh1;
        float a2 = w20 * h0 + w21 * h1 + bh2;
        float a3 = w30 * h0 + w31 * h1 + bh3;
        float a4 = w40 * h0 + w41 * h1 + bh4;
        float a5 = w50 * h0 + w51 * h1 + bh5;

        float r0 = sigf(q0 + a0);
        float r1 = sigf(q1 + a1);
        float z0 = sigf(q2 + a2);
        float z1 = sigf(q3 + a3);
        float n0 = tanh_ex(q4 + r0 * a4);
        float n1 = tanh_ex(q5 + r1 * a5);

        h0 = (1.0f - z0) * n0 + z0 * h0;
        h1 = (1.0f - z1) * n1 + z1 * h1;
    }

    out[b] = fw0 * h0 + fw1 * h1 + fb;
}

extern "C" void kernel_launch(void* const* d_in, const int* in_sizes, int n_in,
                              void* d_out, int out_size) {
    const float* x   = (const float*)d_in[0];
    const float* Wih = (const float*)d_in[1];
    const float* Whh = (const float*)d_in[2];
    const float* bih = (const float*)d_in[3];
    const float* bhh = (const float*)d_in[4];
    const float* fcw = (const float*)d_in[5];
    const float* fcb = (const float*)d_in[6];
    float* out = (float*)d_out;

    (void)in_sizes; (void)n_in; (void)out_size;

    gru_proj<<<K1_GRID, K1_THR>>>(x, Wih, bih);
    gru_recur<<<B_TOT / 128, 128>>>(Whh, bhh, fcw, fcb, out);
}